// round 9
// baseline (speedup 1.0000x reference)
#include <cuda_runtime.h>
#include <math.h>

// Scratch for per-query MLP weights (N x cols). 4096*80 floats = 1.25 MB.
__device__ float g_weights[4096 * 80];

// ===========================================================================
// GEMM (fast path, dim=256, cols=65): weights = q @ Wg + bg.
// 300 CTAs x 256 threads, 8 n per CTA (2 CTAs/SM -> 16 warps of latency
// hiding). K-split: warp w owns d in [32w, 32w+32). Wg read from L2
// (coalesced scalar LDGs, unroll-8 for MLP). q transposed in smem
// (stride 8; LDS.128 broadcasts). Partials tree-reduced through smem.
// ===========================================================================
#define GSQ   0                    // sqT: 256 x 8          = 2048 floats
#define GPR   2048                 // partials: 8*8 x 66    = 4224 floats
#define GTOT  6272

__global__ void __launch_bounds__(256)
posmlp_gemm8_kernel(const float* __restrict__ q,
                    const float* __restrict__ Wg,
                    const float* __restrict__ bg,
                    float* __restrict__ w_out) {
    extern __shared__ float sm[];
    const int n0   = blockIdx.x * 8;
    const int tid  = threadIdx.x;
    const int w    = tid >> 5;
    const int l    = tid & 31;

    // Stage q transposed: sqT[d*8 + nn] = q[(n0+nn)*256 + d].
    #pragma unroll
    for (int i = tid; i < 2048; i += 256) {
        const int nn = i >> 8;
        const int d  = i & 255;
        sm[GSQ + d * 8 + nn] = q[(size_t)n0 * 256 + i];
    }
    __syncthreads();

    const int d0 = w * 32;
    float2 acc[8];
    #pragma unroll
    for (int nn = 0; nn < 8; nn++) acc[nn] = make_float2(0.f, 0.f);
    float acc64[8];
    #pragma unroll
    for (int nn = 0; nn < 8; nn++) acc64[nn] = 0.f;

    #pragma unroll
    for (int db = 0; db < 32; db += 8) {
        float wpx[8], wpy[8], w64[8];
        #pragma unroll
        for (int j = 0; j < 8; j++) {
            const size_t base = (size_t)(d0 + db + j) * 65;
            wpx[j] = Wg[base + 2 * l];
            wpy[j] = Wg[base + 2 * l + 1];
            w64[j] = Wg[base + 64];
        }
        #pragma unroll
        for (int j = 0; j < 8; j++) {
            const int d = d0 + db + j;
            const float4 qa = *reinterpret_cast<const float4*>(&sm[GSQ + d * 8 + 0]);
            const float4 qb = *reinterpret_cast<const float4*>(&sm[GSQ + d * 8 + 4]);
            const float qv[8] = {qa.x, qa.y, qa.z, qa.w, qb.x, qb.y, qb.z, qb.w};
            #pragma unroll
            for (int nn = 0; nn < 8; nn++) {
                acc[nn].x = fmaf(qv[nn], wpx[j], acc[nn].x);
                acc[nn].y = fmaf(qv[nn], wpy[j], acc[nn].y);
            }
            if (l == 0) {
                #pragma unroll
                for (int nn = 0; nn < 8; nn++)
                    acc64[nn] = fmaf(qv[nn], w64[j], acc64[nn]);
            }
        }
    }

    #pragma unroll
    for (int nn = 0; nn < 8; nn++) {
        *reinterpret_cast<float2*>(&sm[GPR + (w * 8 + nn) * 66 + 2 * l]) = acc[nn];
    }
    if (l == 0) {
        #pragma unroll
        for (int nn = 0; nn < 8; nn++) sm[GPR + (w * 8 + nn) * 66 + 64] = acc64[nn];
    }
    __syncthreads();

    for (int o = tid; o < 520; o += 256) {
        const int nn = o / 65;
        const int c  = o - nn * 65;
        float s = 0.f;
        #pragma unroll
        for (int w8 = 0; w8 < 8; w8++) s += sm[GPR + (w8 * 8 + nn) * 66 + c];
        w_out[(size_t)(n0 + nn) * 65 + c] = s + bg[c];
    }
}

// ===========================================================================
// Main kernel (H=W=64, hidden=16): breakpoint/prefix sweep, v3.
// One CTA per n, 256 threads; thread t: row y=t>>2, 16 px at 16*(t&3).
// Global-x formulation: unit k contributes alpha*xg + beta for xg in its
// active half-line. Packed table {e0=w0*tx+b1, w1, alpha=w2*s, inv=1/s}:
// c = fma(rel_y, w1, e0); u = c*inv (= -breakpoint); beta = alpha*u = w2*c.
// s~0 handled by tiny-slope substitution at table build (no special case).
// Branchless bin index via floor (F2I.RM); RMW only for strictly in-window
// breakpoints; clean warps (__all_sync vote) skip the sweep LDS entirely.
// ===========================================================================
__global__ void __launch_bounds__(256)
posmlp_bp16_kernel(const float* __restrict__ pos,
                   const float* __restrict__ wts,
                   float* __restrict__ out) {
    __shared__ float  sw[65];
    __shared__ float4 tab[16];
    __shared__ float2 bins[17 * 256];

    const int n   = blockIdx.x;
    const int tid = threadIdx.x;

    if (tid < 65) sw[tid] = wts[(size_t)n * 65 + tid];
    const float4 p = *reinterpret_cast<const float4*>(&pos[(size_t)n * 4]);
    const float inv_bw = 1.0f / p.z;
    const float inv_bh = 1.0f / p.w;
    const float sx = inv_bw * (1.0f / 64.0f);
    const float tx = (0.5f * (1.0f / 64.0f) - p.x) * inv_bw;
    __syncthreads();

    if (tid < 16) {
        const int k = tid;
        const float w0 = sw[k];
        const float w2 = sw[48 + k];
        float s = w0 * sx;
        float alpha, inv;
        if (fabsf(s) < 1e-18f) {
            const float sgn = (s >= 0.f) ? 1.0f : -1.0f;
            alpha = w2 * (sgn * 1e-30f);
            inv   = sgn * 1e30f;
        } else {
            alpha = w2 * s;
            inv   = __fdividef(1.0f, s);
        }
        tab[k] = make_float4(fmaf(w0, tx, sw[32 + k]), sw[16 + k], alpha, inv);
    }
    // Zero bins via float4 (17*128 float4 total).
    {
        float4* b4 = reinterpret_cast<float4*>(bins);
        for (int i = tid; i < 17 * 128; i += 256)
            b4[i] = make_float4(0.f, 0.f, 0.f, 0.f);
    }
    __syncthreads();

    const int y  = tid >> 2;
    const int qd = tid & 3;
    const float Lf = (float)(16 * qd);

    const float rel_y = (((float)y + 0.5f) * (1.0f / 64.0f) - p.y) * inv_bh;

    float A0 = 0.f;
    float B0 = sw[64];
    bool  nz = false;

    #pragma unroll
    for (int k = 0; k < 16; k++) {
        const float4 T = tab[k];            // e0, w1, alpha, inv
        const float c    = fmaf(rel_y, T.y, T.x);
        const float u    = c * T.w;         // = -breakpoint (global x)
        const float beta = T.z * u;         // = w2 * c
        float v = u + Lf;
        v = fminf(fmaxf(v, -16.5f), 0.5f);
        int bl = -__float2int_rd(v);
        bl = min(bl, 16);

        const bool neg = (T.w < 0.f);
        const bool a0p = neg ? (bl > 0) : (bl == 0);
        if (a0p) { A0 += T.z; B0 += beta; }
        if (bl > 0 && bl < 16) {
            const float sa = neg ? -T.z  : T.z;
            const float sb = neg ? -beta : beta;
            float2 vv = bins[bl * 256 + tid];
            vv.x += sa; vv.y += sb;
            bins[bl * 256 + tid] = vv;
            nz = true;
        }
    }

    float* orow = out + (((size_t)n * 64 + y) * 64 + qd * 16);

    if (__all_sync(0xffffffffu, !nz)) {
        // Clean warp: output is a single linear function across the window.
        #pragma unroll
        for (int xi = 0; xi < 16; xi += 4) {
            float4 res;
            res.x = fmaf(A0, Lf + (float)(xi + 0), B0);
            res.y = fmaf(A0, Lf + (float)(xi + 1), B0);
            res.z = fmaf(A0, Lf + (float)(xi + 2), B0);
            res.w = fmaf(A0, Lf + (float)(xi + 3), B0);
            *reinterpret_cast<float4*>(orow + xi) = res;
        }
    } else {
        float A = A0, B = B0;
        #pragma unroll
        for (int xi = 0; xi < 16; xi += 4) {
            float4 res;
            float* rp = &res.x;
            #pragma unroll
            for (int j = 0; j < 4; j++) {
                const float2 d = bins[(xi + j) * 256 + tid];
                A += d.x;
                B += d.y;
                rp[j] = fmaf(A, Lf + (float)(xi + j), B);
            }
            *reinterpret_cast<float4*>(orow + xi) = res;
        }
    }
}

// ===========================================================================
// Fallback path (other shapes).
// ===========================================================================
__global__ void posmlp_gemm_kernel(const float* __restrict__ q,
                                   const float* __restrict__ Wg,
                                   const float* __restrict__ bg,
                                   float* __restrict__ w_out,
                                   int dim, int cols) {
    extern __shared__ float sqf[];
    const int n = blockIdx.x;
    const float* qr = q + (size_t)n * dim;
    for (int d = threadIdx.x; d < dim; d += blockDim.x) sqf[d] = qr[d];
    __syncthreads();
    for (int j = threadIdx.x; j < cols; j += blockDim.x) {
        float acc = bg[j];
        #pragma unroll 8
        for (int d = 0; d < dim; d++) {
            acc = fmaf(sqf[d], Wg[(size_t)d * cols + j], acc);
        }
        w_out[(size_t)n * cols + j] = acc;
    }
}

__global__ void posmlp_generic_kernel(const float* __restrict__ pos,
                                      const float* __restrict__ wts,
                                      float* __restrict__ out,
                                      int H, int W, int h, int cols) {
    const int n = blockIdx.x;
    const float* w = wts + (size_t)n * cols;
    const float cx = pos[(size_t)n * 4 + 0];
    const float cy = pos[(size_t)n * 4 + 1];
    const float bw = pos[(size_t)n * 4 + 2];
    const float bh = pos[(size_t)n * 4 + 3];
    const float b2 = w[4 * h];
    const int total = H * W;
    for (int idx = threadIdx.x; idx < total; idx += blockDim.x) {
        const int yy = idx / W;
        const int xx = idx - yy * W;
        const float rel_x = (((float)xx + 0.5f) / (float)W - cx) / bw;
        const float rel_y = (((float)yy + 0.5f) / (float)H - cy) / bh;
        float acc = b2;
        for (int k = 0; k < h; k++) {
            float pre = fmaf(rel_x, w[k], fmaf(rel_y, w[h + k], w[2 * h + k]));
            acc = fmaf(fmaxf(pre, 0.0f), w[3 * h + k], acc);
        }
        out[(size_t)n * total + idx] = acc;
    }
}

extern "C" void kernel_launch(void* const* d_in, const int* in_sizes, int n_in,
                              void* d_out, int out_size) {
    const float* pos = (const float*)d_in[0];
    const float* q   = (const float*)d_in[1];
    const float* Wg  = (const float*)d_in[2];
    const float* bg  = (const float*)d_in[3];
    float* out = (float*)d_out;

    const int N    = in_sizes[0] / 4;          // rows of pos
    const int dim  = in_sizes[1] / N;          // query dim
    const int cols = in_sizes[3];              // 4*h + 1
    const int HW   = out_size / N;
    const int H    = (int)(sqrt((double)HW) + 0.5);
    const int h    = (cols - 1) / 4;

    float* w_scratch;
    cudaGetSymbolAddress((void**)&w_scratch, g_weights);

    if (H == 64 && h == 16 && cols == 65 && dim == 256 && (N % 8) == 0) {
        const int smem_bytes = GTOT * sizeof(float);  // ~25 KB
        cudaFuncSetAttribute(posmlp_gemm8_kernel,
                             cudaFuncAttributeMaxDynamicSharedMemorySize, smem_bytes);
        posmlp_gemm8_kernel<<<N / 8, 256, smem_bytes>>>(q, Wg, bg, w_scratch);
        posmlp_bp16_kernel<<<N, 256>>>(pos, w_scratch, out);
    } else {
        posmlp_gemm_kernel<<<N, 256, dim * sizeof(float)>>>(q, Wg, bg, w_scratch, dim, cols);
        posmlp_generic_kernel<<<N, 256>>>(pos, w_scratch, out, H, H, h, cols);
    }
}